// round 4
// baseline (speedup 1.0000x reference)
#include <cuda_runtime.h>
#include <math.h>

// ---------------- problem constants ----------------
#define BB 16
#define AA 3
#define CC 80
#define HH 76
#define WW 76
#define TT 50
#define HWP (HH * WW)              // 5776
#define NCELL (BB * AA * HWP)      // 277248
#define NCH (5 + CC)               // 85
#define RED_THREADS 256
#define NB_RED ((NCELL + RED_THREADS - 1) / RED_THREADS)   // 1083 (exact: 1083*256 = 277248)

// anchors / stride = [[1.25,1.625],[2.0,3.75],[4.125,2.875]]
__constant__ float c_aw[3] = {1.25f, 2.0f, 4.125f};
__constant__ float c_ah[3] = {1.625f, 3.75f, 2.875f};

// ---------------- scratch (no allocation allowed) ----------------
struct Rec { float tx, ty, tw, th; unsigned long long c0, c1; };

__device__ int   g_tag[NCELL];        // bit0 = noobj-zero flag, bits 1.. = record id + 1
__device__ Rec   g_rec[BB * TT];      // compact per-target records
__device__ float g_part[NB_RED * 9];  // per-block partial sums

// ---------------- helpers ----------------
__device__ __forceinline__ float bce_f(float p, float t) {
    // -(t*max(log p,-100) + (1-t)*max(log(1-p),-100)) ; logf(0)=-inf -> clamped
    return -(t * fmaxf(logf(p), -100.0f) + (1.0f - t) * fmaxf(logf(1.0f - p), -100.0f));
}

__device__ __forceinline__ float sigm(float x) { return 1.0f / (1.0f + expf(-x)); }

// Deterministic block reduction of 9 values. On return, thread 0 holds totals in v[].
__device__ __forceinline__ void block_reduce9(float* v) {
    __shared__ float sh[8][9];
    int lane = threadIdx.x & 31;
    int wid  = threadIdx.x >> 5;
#pragma unroll
    for (int k = 0; k < 9; k++) {
        float x = v[k];
#pragma unroll
        for (int o = 16; o; o >>= 1) x += __shfl_down_sync(0xffffffffu, x, o);
        if (lane == 0) sh[wid][k] = x;
    }
    __syncthreads();
    if (wid == 0) {
        int nw = blockDim.x >> 5;
#pragma unroll
        for (int k = 0; k < 9; k++) {
            float x = (lane < nw) ? sh[lane][k] : 0.0f;
#pragma unroll
            for (int o = 16; o; o >>= 1) x += __shfl_down_sync(0xffffffffu, x, o);
            if (lane == 0) v[k] = x;
        }
    }
}

// ---------------- kernel 1: clear tag array ----------------
__global__ void k_clear() {
    int i = blockIdx.x * blockDim.x + threadIdx.x;
    int4* p = (int4*)g_tag;
    if (i < NCELL / 4) p[i] = make_int4(0, 0, 0, 0);
}

// ---------------- kernel 2: build targets ----------------
// One thread per batch, serial over targets -> exact "last update wins" ordering
// for mask/tx/ty/tw/th; class bits are unioned (matches .at[].set(1.0)).
__global__ void k_build(const float* __restrict__ tgt) {
    int b = threadIdx.x;
    if (b >= BB) return;
    for (int t = 0; t < TT; t++) {
        const float* tp = tgt + (b * TT + t) * 5;
        float cls = tp[0], cx = tp[1], cy = tp[2], cw = tp[3], chv = tp[4];
        if (cls + cx + cy + cw + chv == 0.0f) continue;  // valid check
        float gx = cx * WW, gy = cy * HH, gw = cw * WW, gh = chv * HH;
        int gi = (int)gx, gj = (int)gy;

        float a1 = (gw + 1.0f) * (gh + 1.0f);
        float iou[3];
        int best = 0;
#pragma unroll
        for (int a = 0; a < 3; a++) {
            float iw = fmaxf(fminf(gw, c_aw[a]) + 1.0f, 0.0f);
            float ih = fmaxf(fminf(gh, c_ah[a]) + 1.0f, 0.0f);
            float inter = iw * ih;
            float a2 = (c_aw[a] + 1.0f) * (c_ah[a] + 1.0f);
            iou[a] = inter / (a1 + a2 - inter + 1e-16f);
            if (iou[a] > iou[best]) best = a;   // first-max tie-break (argmax)
        }
        // noobj zeroing (no bounds gate in reference beyond drop semantics)
#pragma unroll
        for (int a = 0; a < 3; a++) {
            if (iou[a] > 0.5f) {
                long nm = (((long)(b * AA + a) * HH + gj) * WW + gi);
                if (nm >= 0 && nm < NCELL) g_tag[nm] |= 1;
            }
        }
        if (gj < HH && gi < WW) {
            long cell = (((long)(b * AA + best) * HH + gj) * WW + gi);
            if (cell >= 0 && cell < NCELL) {
                int tag = g_tag[(int)cell];
                int rid = tag >> 1;
                Rec* r;
                if (rid == 0) {
                    rid = b * TT + t + 1;
                    g_tag[(int)cell] = (rid << 1) | (tag & 1);
                    r = &g_rec[rid - 1];
                    r->c0 = 0ull; r->c1 = 0ull;
                } else {
                    r = &g_rec[rid - 1];  // collision: overwrite box, union class bits
                }
                r->tx = gx - (float)gi;
                r->ty = gy - (float)gj;
                r->tw = logf(gw / c_aw[best] + 1e-16f);
                r->th = logf(gh / c_ah[best] + 1e-16f);
                int ci = (int)cls;
                if (ci >= 0 && ci < 64)        r->c0 |= (1ull << ci);
                else if (ci >= 64 && ci < CC)  r->c1 |= (1ull << (ci - 64));
            }
        }
    }
}

// ---------------- kernel 3: main reduction ----------------
// v[0]=sum bce_x, v[1]=bce_y, v[2]=sq_w, v[3]=sq_h,
// v[4]=bce(conf,1) masked, v[5]=bce(conf,0) where noobj=1,
// v[6]=cls bce sum (masked), v[7]=n_m count, v[8]=noobj-zero count
__global__ void __launch_bounds__(RED_THREADS) k_reduce(const float* __restrict__ inp) {
    int cell = blockIdx.x * blockDim.x + threadIdx.x;
    float v[9];
#pragma unroll
    for (int k = 0; k < 9; k++) v[k] = 0.0f;

    if (cell < NCELL) {
        int tag  = g_tag[cell];
        int gidx = cell / HWP;          // b*A + a
        int rr   = cell - gidx * HWP;   // j*W + i
        const float* p = inp + (size_t)gidx * NCH * HWP + rr;

        float conf = sigm(p[(size_t)4 * HWP]);
        if ((tag & 1) == 0) {
            v[5] = -fmaxf(logf(1.0f - conf), -100.0f);   // bce(conf, 0)
        } else {
            v[8] = 1.0f;
        }
        int rid = tag >> 1;
        if (rid) {
            Rec rec = g_rec[rid - 1];
            float xs = sigm(p[0]);
            float ys = sigm(p[(size_t)1 * HWP]);
            v[0] = bce_f(xs, rec.tx);
            v[1] = bce_f(ys, rec.ty);
            float dw = p[(size_t)2 * HWP] - rec.tw;
            float dh = p[(size_t)3 * HWP] - rec.th;
            v[2] = dw * dw;
            v[3] = dh * dh;
            v[4] = -fmaxf(logf(conf), -100.0f);          // bce(conf, 1)
            v[7] = 1.0f;
            float sc = 0.0f;
#pragma unroll 4
            for (int c = 0; c < CC; c++) {
                float pc = sigm(p[(size_t)(5 + c) * HWP]);
                float tb = (c < 64) ? (float)((rec.c0 >> c) & 1ull)
                                    : (float)((rec.c1 >> (c - 64)) & 1ull);
                sc += bce_f(pc, tb);
            }
            v[6] = sc;
        }
    }
    block_reduce9(v);
    if (threadIdx.x == 0) {
#pragma unroll
        for (int k = 0; k < 9; k++) g_part[blockIdx.x * 9 + k] = v[k];
    }
}

// ---------------- kernel 4: final combine ----------------
__global__ void __launch_bounds__(256) k_final(float* __restrict__ out) {
    float v[9];
#pragma unroll
    for (int k = 0; k < 9; k++) v[k] = 0.0f;
    for (int i = threadIdx.x; i < NB_RED; i += blockDim.x) {
#pragma unroll
        for (int k = 0; k < 9; k++) v[k] += g_part[i * 9 + k];
    }
    block_reduce9(v);
    if (threadIdx.x == 0) {
        float n_m  = v[7];
        float n_nm = (float)NCELL - v[8];
        float invN = 1.0f / (float)NCELL;
        float lx = v[0] * invN / n_m;
        float ly = v[1] * invN / n_m;
        float lw = v[2] * invN / n_m;
        float lh = v[3] * invN / n_m;
        float lconf = v[4] * invN / n_m + 0.5f * v[5] * invN / n_nm;
        float lcls  = v[6] / (n_m * (float)CC) / n_m;
        float loss  = 2.5f * (lx + ly) + 2.5f * (lw + lh) + lconf + lcls;
        out[0] = loss;
        out[1] = lx;
        out[2] = ly;
        out[3] = lw;
        out[4] = lh;
        out[5] = lconf;
        out[6] = lcls;
    }
}

// ---------------- launch ----------------
extern "C" void kernel_launch(void* const* d_in, const int* in_sizes, int n_in,
                              void* d_out, int out_size) {
    const float* inp = (const float*)d_in[0];   // (B, A*(5+C), H, W) fp32
    const float* tgt = (const float*)d_in[1];   // (B, T, 5) fp32
    float* out = (float*)d_out;                 // 7 fp32 scalars
    (void)in_sizes; (void)n_in; (void)out_size;

    k_clear<<<(NCELL / 4 + 255) / 256, 256>>>();
    k_build<<<1, 32>>>(tgt);
    k_reduce<<<NB_RED, RED_THREADS>>>(inp);
    k_final<<<1, 256>>>(out);
}

// round 5
// speedup vs baseline: 1.1919x; 1.1919x over previous
#include <cuda_runtime.h>
#include <math.h>

// ---------------- problem constants ----------------
#define BB 16
#define AA 3
#define CC 80
#define HH 76
#define WW 76
#define TT 50
#define HWP (HH * WW)               // 5776
#define NCELL (BB * AA * HWP)       // 277248
#define NCH (5 + CC)                // 85
#define NREC (BB * TT)              // 800

#define N4 (HWP / 4)                // 1444 float4 per plane
#define NPLANE (BB * AA)            // 48 conf planes
#define CONF_ITEMS (NPLANE * N4)    // 69312
#define NB_CONF ((CONF_ITEMS + 255) / 256)   // 271
#define NB_REC  (NREC / 8)                   // 100 (8 warps/block, 1 rec/warp)
#define NB_FLAG BB                           // 16
#define GRID (NB_CONF + NB_REC + NB_FLAG)    // 387

// anchors / stride = [[1.25,1.625],[2.0,3.75],[4.125,2.875]]
__constant__ float c_aw[3] = {1.25f, 2.0f, 4.125f};
__constant__ float c_ah[3] = {1.625f, 3.75f, 2.875f};

// ---------------- scratch (no allocation allowed) ----------------
struct Rec { int cell; float tx, ty, tw, th; unsigned long long c0, c1; };

__device__ Rec   g_rec[NREC];
__device__ int   g_flag[BB * 152];   // flagged cells (with dups), per-batch slots
__device__ int   g_nflag[BB];
__device__ float g_part[GRID * 9];
__device__ int   g_count = 0;        // ticket for last-block election (reset each run)

// ---------------- helpers ----------------
// softplus(z) = log(1+e^z) = -log(1-sigmoid(z)); clamp matches max(log(.),-100)
__device__ __forceinline__ float spc(float z) {
    return fminf(__logf(1.0f + __expf(z)), 100.0f);
}

// Deterministic block reduction of 9 values. Thread 0 ends with totals in v[].
__device__ __forceinline__ void block_reduce9(float* v) {
    __shared__ float sh[8][9];
    int lane = threadIdx.x & 31;
    int wid  = threadIdx.x >> 5;
#pragma unroll
    for (int k = 0; k < 9; k++) {
        float x = v[k];
#pragma unroll
        for (int o = 16; o; o >>= 1) x += __shfl_down_sync(0xffffffffu, x, o);
        if (lane == 0) sh[wid][k] = x;
    }
    __syncthreads();
    if (wid == 0) {
#pragma unroll
        for (int k = 0; k < 9; k++) {
            float x = (lane < 8) ? sh[lane][k] : 0.0f;
#pragma unroll
            for (int o = 4; o; o >>= 1) x += __shfl_down_sync(0xffffffffu, x, o);
            if (lane == 0) v[k] = x;
        }
    }
}

// ---------------- kernel 1: build targets (1 block) ----------------
// 256 threads stage all targets into shared; 16 serial workers (1/batch)
// reproduce exact scatter semantics: last-update-wins for box fields,
// union for class bits; flags emitted WITH duplicates (dedup'd later).
__global__ void __launch_bounds__(256) k_build(const float* __restrict__ tgt) {
    __shared__ float s_tgt[NREC * 5];   // 16 KB
    for (int i = threadIdx.x; i < NREC * 5; i += 256) s_tgt[i] = tgt[i];
    __syncthreads();

    int b = threadIdx.x;
    if (b >= BB) return;

    // invalidate this batch's record slots
    for (int t = 0; t < TT; t++) g_rec[b * TT + t].cell = -1;

    int nf = 0;
    int mycell[TT], myslot[TT];
    int nmy = 0;

    for (int t = 0; t < TT; t++) {
        const float* tp = &s_tgt[(b * TT + t) * 5];
        float cls = tp[0], cx = tp[1], cy = tp[2], cw = tp[3], chv = tp[4];
        if (cls + cx + cy + cw + chv == 0.0f) continue;  // valid check

        float gx = cx * WW, gy = cy * HH, gw = cw * WW, gh = chv * HH;
        int gi = (int)gx, gj = (int)gy;

        float a1 = (gw + 1.0f) * (gh + 1.0f);
        float iou[3];
        int best = 0;
#pragma unroll
        for (int a = 0; a < 3; a++) {
            float iw = fmaxf(fminf(gw, c_aw[a]) + 1.0f, 0.0f);
            float ih = fmaxf(fminf(gh, c_ah[a]) + 1.0f, 0.0f);
            float inter = iw * ih;
            float a2 = (c_aw[a] + 1.0f) * (c_ah[a] + 1.0f);
            iou[a] = inter / (a1 + a2 - inter + 1e-16f);
            if (iou[a] > iou[best]) best = a;   // first-max tie-break
        }
        // noobj flags (scatter-drop semantics -> just bound check)
#pragma unroll
        for (int a = 0; a < 3; a++) {
            if (iou[a] > 0.5f) {
                long nm = (((long)(b * AA + a) * HH + gj) * WW + gi);
                if (nm >= 0 && nm < NCELL) g_flag[b * 152 + (nf++)] = (int)nm;
            }
        }
        if (gj >= 0 && gj < HH && gi >= 0 && gi < WW) {
            int cell = ((b * AA + best) * HH + gj) * WW + gi;
            int slot = -1;
            for (int k = 0; k < nmy; k++)
                if (mycell[k] == cell) { slot = myslot[k]; break; }
            unsigned long long c0, c1;
            if (slot < 0) {
                slot = b * TT + t;
                mycell[nmy] = cell; myslot[nmy] = slot; nmy++;
                c0 = 0ull; c1 = 0ull;
            } else {                       // collision: overwrite box, union cls
                c0 = g_rec[slot].c0; c1 = g_rec[slot].c1;
            }
            Rec r;
            r.cell = cell;
            r.tx = gx - (float)gi;
            r.ty = gy - (float)gj;
            r.tw = __logf(gw / c_aw[best] + 1e-16f);
            r.th = __logf(gh / c_ah[best] + 1e-16f);
            int ci = (int)cls;
            if (ci >= 0 && ci < 64)       c0 |= (1ull << ci);
            else if (ci >= 64 && ci < CC) c1 |= (1ull << (ci - 64));
            r.c0 = c0; r.c1 = c1;
            g_rec[slot] = r;
        }
    }
    g_nflag[b] = nf;
}

// ---------------- kernel 2: everything else, one wave ----------------
// v[0..3]=x/y/w/h sums, v[4]=bce(conf,1) masked, v[5]=sum softplus(z4)
// global minus flagged, v[6]=cls sum, v[7]=n_m, v[8]=n_flagged(dedup)
__global__ void __launch_bounds__(256) k_main(const float* __restrict__ inp,
                                              float* __restrict__ out) {
    int bid = blockIdx.x;
    int tid = threadIdx.x;
    float v[9];
#pragma unroll
    for (int k = 0; k < 9; k++) v[k] = 0.0f;

    if (bid < NB_CONF) {
        // ---- conf planes: coalesced float4 over channel 4 of each (b,a) ----
        int idx = bid * 256 + tid;
        if (idx < CONF_ITEMS) {
            int plane = idx / N4;
            int off   = idx - plane * N4;
            const float4* p4 = (const float4*)(inp + ((size_t)plane * NCH + 4) * HWP);
            float4 z = __ldg(p4 + off);
            v[5] = spc(z.x) + spc(z.y) + spc(z.z) + spc(z.w);
        }
    } else if (bid < NB_CONF + NB_REC) {
        // ---- masked records: one warp per record, lanes split channels ----
        int rec  = (bid - NB_CONF) * 8 + (tid >> 5);
        int lane = tid & 31;
        Rec r = g_rec[rec];                    // uniform addr -> broadcast
        if (r.cell >= 0) {
            int gidx = r.cell / HWP;
            int rr   = r.cell - gidx * HWP;
            const float* p = inp + (size_t)gidx * NCH * HWP + rr;
#pragma unroll
            for (int k = 0; k < 3; k++) {
                int ch = lane + 32 * k;
                if (ch < NCH) {
                    float z = __ldg(p + (size_t)ch * HWP);
                    if (ch >= 5) {
                        int c = ch - 5;
                        float t = (c < 64) ? (float)((r.c0 >> c) & 1ull)
                                           : (float)((r.c1 >> (c - 64)) & 1ull);
                        v[6] += spc(z) - t * z;            // bce(sigm(z), t)
                    } else if (ch == 0) {
                        v[0] = spc(z) - r.tx * z;
                    } else if (ch == 1) {
                        v[1] = spc(z) - r.ty * z;
                    } else if (ch == 2) {
                        float d = z - r.tw; v[2] = d * d;
                    } else if (ch == 3) {
                        float d = z - r.th; v[3] = d * d;
                    } else {                               // ch == 4
                        v[4] = spc(-z);                    // bce(conf, 1)
                    }
                }
            }
            if (lane == 0) v[7] = 1.0f;                    // n_m count
        }
    } else {
        // ---- flagged-cell corrections: dedup + subtract softplus ----
        int b = bid - (NB_CONF + NB_REC);
        __shared__ int s_f[152];
        __shared__ int s_cnt;
        if (tid == 0) s_cnt = g_nflag[b];
        __syncthreads();
        int cnt = s_cnt;
        if (tid < cnt) s_f[tid] = g_flag[b * 152 + tid];
        __syncthreads();
        if (tid < cnt) {
            int cell = s_f[tid];
            bool dup = false;
            for (int j = 0; j < tid; j++)
                if (s_f[j] == cell) { dup = true; break; }
            if (!dup) {
                int gidx = cell / HWP;
                int rr   = cell - gidx * HWP;
                float z = __ldg(inp + ((size_t)gidx * NCH + 4) * HWP + rr);
                v[5] = -spc(z);       // remove from global noobj sum
                v[8] = 1.0f;          // flagged (unique) count
            }
        }
    }

    block_reduce9(v);
    __shared__ int s_amlast;
    if (tid == 0) {
#pragma unroll
        for (int k = 0; k < 9; k++) g_part[bid * 9 + k] = v[k];
        __threadfence();
        int t = atomicAdd(&g_count, 1);
        s_amlast = (t == GRID - 1);
    }
    __syncthreads();

    if (s_amlast) {
        float w[9];
#pragma unroll
        for (int k = 0; k < 9; k++) w[k] = 0.0f;
        for (int i = tid; i < GRID; i += 256) {
#pragma unroll
            for (int k = 0; k < 9; k++) w[k] += g_part[i * 9 + k];
        }
        block_reduce9(w);
        if (tid == 0) {
            float n_m  = w[7];
            float n_nm = (float)NCELL - w[8];
            float invN = 1.0f / (float)NCELL;
            float lx = w[0] * invN / n_m;
            float ly = w[1] * invN / n_m;
            float lw = w[2] * invN / n_m;
            float lh = w[3] * invN / n_m;
            float lconf = w[4] * invN / n_m + 0.5f * w[5] * invN / n_nm;
            float lcls  = w[6] / (n_m * (float)CC) / n_m;
            float loss  = 2.5f * (lx + ly) + 2.5f * (lw + lh) + lconf + lcls;
            out[0] = loss;
            out[1] = lx;
            out[2] = ly;
            out[3] = lw;
            out[4] = lh;
            out[5] = lconf;
            out[6] = lcls;
            g_count = 0;             // reset ticket for next graph replay
        }
    }
}

// ---------------- launch ----------------
extern "C" void kernel_launch(void* const* d_in, const int* in_sizes, int n_in,
                              void* d_out, int out_size) {
    const float* inp = (const float*)d_in[0];   // (B, A*(5+C), H, W) fp32
    const float* tgt = (const float*)d_in[1];   // (B, T, 5) fp32
    float* out = (float*)d_out;                 // 7 fp32 scalars
    (void)in_sizes; (void)n_in; (void)out_size;

    k_build<<<1, 256>>>(tgt);
    k_main<<<GRID, 256>>>(inp, out);
}

// round 6
// speedup vs baseline: 4.0518x; 3.3995x over previous
#include <cuda_runtime.h>
#include <math.h>

// ---------------- problem constants ----------------
#define BB 16
#define AA 3
#define CC 80
#define HH 76
#define WW 76
#define TT 50
#define HWP (HH * WW)               // 5776
#define NCELL (BB * AA * HWP)       // 277248
#define NCH (5 + CC)                // 85
#define NREC (BB * TT)              // 800
#define NFLAG (NREC * 3)            // 2400 (3 anchors per target)

#define N4 (HWP / 4)                // 1444 float4 per plane
#define NPLANE (BB * AA)            // 48 conf planes
#define CONF_ITEMS (NPLANE * N4)    // 69312 float4 items
#define NB_CONF 136                 // 136 * 512 = 69632 >= 69312 (2 items/thread)
#define NB_REC  (NREC / 8)          // 100 blocks, 8 warps/block, 1 rec/warp
#define GRID (1 + NB_CONF + NB_REC) // 237

// anchors / stride = [[1.25,1.625],[2.0,3.75],[4.125,2.875]]
__constant__ float c_aw[3] = {1.25f, 2.0f, 4.125f};
__constant__ float c_ah[3] = {1.625f, 3.75f, 2.875f};

// ---------------- scratch (no allocation allowed) ----------------
struct Rec { int cell; float tx, ty, tw, th; unsigned long long c0, c1; };

__device__ Rec   g_rec[NREC];
__device__ float g_part[GRID * 9];
__device__ int   g_count = 0;   // ticket for last-block election (reset each run)
__device__ int   g_ready = 0;   // build-done flag (reset each run)

// ---------------- helpers ----------------
// softplus(z) = -log(1 - sigmoid(z)); clamp matches max(log(.), -100)
__device__ __forceinline__ float spc(float z) {
    return fminf(__logf(1.0f + __expf(z)), 100.0f);
}

// Deterministic block reduction of 9 values. Thread 0 ends with totals in v[].
__device__ __forceinline__ void block_reduce9(float* v) {
    __shared__ float sh[8][9];
    int lane = threadIdx.x & 31;
    int wid  = threadIdx.x >> 5;
#pragma unroll
    for (int k = 0; k < 9; k++) {
        float x = v[k];
#pragma unroll
        for (int o = 16; o; o >>= 1) x += __shfl_down_sync(0xffffffffu, x, o);
        if (lane == 0) sh[wid][k] = x;
    }
    __syncthreads();
    if (wid == 0) {
#pragma unroll
        for (int k = 0; k < 9; k++) {
            float x = (lane < 8) ? sh[lane][k] : 0.0f;
#pragma unroll
            for (int o = 4; o; o >>= 1) x += __shfl_down_sync(0xffffffffu, x, o);
            if (lane == 0) v[k] = x;
        }
    }
}

// ---------------- fused kernel ----------------
// block 0            : parallel target build + flag-dedup corrections
// blocks [1, 1+136)  : conf planes, Σ softplus(z4) over all cells (float4 x2)
// blocks [137, 237)  : masked records, 1 warp/record (spin on g_ready)
//
// partials: v[0..3]=x/y/w/h sums, v[4]=bce(conf,1) masked, v[5]=Σsp(z4)
// (global, minus flagged), v[6]=cls sum, v[7]=n_m, v[8]=n_flagged(unique)
__global__ void __launch_bounds__(256) k_all(const float* __restrict__ inp,
                                             const float* __restrict__ tgt,
                                             float* __restrict__ out) {
    __shared__ int   s_cell[NREC];
    __shared__ int   s_cls[NREC];
    __shared__ float s_tx[NREC], s_ty[NREC], s_tw[NREC], s_th[NREC];
    __shared__ int   s_flag[NFLAG];

    int bid = blockIdx.x;
    int tid = threadIdx.x;
    float v[9];
#pragma unroll
    for (int k = 0; k < 9; k++) v[k] = 0.0f;

    if (bid == 0) {
        // ---------- pass 1: per-target compute into shared ----------
        for (int tg = tid; tg < NREC; tg += 256) {
            const float* tp = tgt + tg * 5;
            float cls = tp[0], cx = tp[1], cy = tp[2], cw = tp[3], chv = tp[4];
            int cell = -1;
            float tx = 0.f, ty = 0.f, tw = 0.f, th = 0.f;
            int fl[3] = {-1, -1, -1};
            if (cls + cx + cy + cw + chv != 0.0f) {       // valid
                int b = tg / TT;
                float gx = cx * WW, gy = cy * HH, gw = cw * WW, gh = chv * HH;
                int gi = (int)gx, gj = (int)gy;
                float a1 = (gw + 1.0f) * (gh + 1.0f);
                float iou[3];
                int best = 0;
#pragma unroll
                for (int a = 0; a < 3; a++) {
                    float iw = fmaxf(fminf(gw, c_aw[a]) + 1.0f, 0.0f);
                    float ih = fmaxf(fminf(gh, c_ah[a]) + 1.0f, 0.0f);
                    float inter = iw * ih;
                    float a2 = (c_aw[a] + 1.0f) * (c_ah[a] + 1.0f);
                    iou[a] = inter / (a1 + a2 - inter + 1e-16f);
                    if (iou[a] > iou[best]) best = a;     // first-max tie-break
                }
#pragma unroll
                for (int a = 0; a < 3; a++) {
                    long nm = (((long)(b * AA + a) * HH + gj) * WW + gi);
                    if (iou[a] > 0.5f && nm >= 0 && nm < NCELL) fl[a] = (int)nm;
                }
                if (gj >= 0 && gj < HH && gi >= 0 && gi < WW) {
                    cell = ((b * AA + best) * HH + gj) * WW + gi;
                    tx = gx - (float)gi;
                    ty = gy - (float)gj;
                    tw = __logf(gw / c_aw[best] + 1e-16f);
                    th = __logf(gh / c_ah[best] + 1e-16f);
                }
            }
            s_cell[tg] = cell;
            s_cls[tg]  = (int)cls;
            s_tx[tg] = tx; s_ty[tg] = ty; s_tw[tg] = tw; s_th[tg] = th;
            s_flag[tg * 3 + 0] = fl[0];
            s_flag[tg * 3 + 1] = fl[1];
            s_flag[tg * 3 + 2] = fl[2];
        }
        __syncthreads();

        // ---------- pass 2: winner resolution (last-wins) + class union ----------
        for (int tg = tid; tg < NREC; tg += 256) {
            Rec r; r.cell = -1;
            int cell = s_cell[tg];
            if (cell >= 0) {
                int base = (tg / TT) * TT;
                bool win = true;
                unsigned long long c0 = 0ull, c1 = 0ull;
                for (int j = base; j < base + TT; j++) {
                    if (s_cell[j] == cell) {
                        if (j > tg) win = false;          // later write wins box
                        int ci = s_cls[j];                // union ALL class bits
                        if (ci >= 0 && ci < 64)       c0 |= (1ull << ci);
                        else if (ci >= 64 && ci < CC) c1 |= (1ull << (ci - 64));
                    }
                }
                if (win) {
                    r.cell = cell;
                    r.tx = s_tx[tg]; r.ty = s_ty[tg];
                    r.tw = s_tw[tg]; r.th = s_th[tg];
                    r.c0 = c0; r.c1 = c1;
                }
            }
            g_rec[tg] = r;
        }
        __syncthreads();
        if (tid == 0) { __threadfence(); atomicExch(&g_ready, 1); }

        // ---------- flag corrections (dedup via shared scan) ----------
        for (int f = tid; f < NFLAG; f += 256) {
            int cell = s_flag[f];
            if (cell >= 0) {
                int base = (f / (TT * 3)) * (TT * 3);     // batch range start
                bool own = true;
                for (int j = base; j < f; j++)
                    if (s_flag[j] == cell) { own = false; break; }
                if (own) {
                    int gidx = cell / HWP;
                    int rr   = cell - gidx * HWP;
                    float z = __ldg(inp + ((size_t)gidx * NCH + 4) * HWP + rr);
                    v[5] -= spc(z);        // remove from global noobj sum
                    v[8] += 1.0f;          // unique flagged count
                }
            }
        }
    } else if (bid <= NB_CONF) {
        // ---------- conf planes: coalesced float4, 2 per thread ----------
        int i0 = (bid - 1) * 512 + tid;
#pragma unroll
        for (int k = 0; k < 2; k++) {
            int idx = i0 + k * 256;
            if (idx < CONF_ITEMS) {
                int plane = idx / N4;
                int off   = idx - plane * N4;
                const float4* p4 = (const float4*)(inp + ((size_t)plane * NCH + 4) * HWP);
                float4 z = __ldg(p4 + off);
                v[5] += spc(z.x) + spc(z.y) + spc(z.z) + spc(z.w);
            }
        }
    } else {
        // ---------- masked records: wait for build, 1 warp/record ----------
        while (((volatile int*)&g_ready)[0] == 0) __nanosleep(64);
        __threadfence();   // acquire: order g_rec reads after flag observation

        int rec  = (bid - 1 - NB_CONF) * 8 + (tid >> 5);
        int lane = tid & 31;
        Rec r = g_rec[rec];                 // uniform addr -> broadcast
        if (r.cell >= 0) {
            int gidx = r.cell / HWP;
            int rr   = r.cell - gidx * HWP;
            const float* p = inp + (size_t)gidx * NCH * HWP + rr;
#pragma unroll
            for (int k = 0; k < 3; k++) {
                int ch = lane + 32 * k;
                if (ch < NCH) {
                    float z = __ldg(p + (size_t)ch * HWP);
                    if (ch >= 5) {
                        int c = ch - 5;
                        float t = (c < 64) ? (float)((r.c0 >> c) & 1ull)
                                           : (float)((r.c1 >> (c - 64)) & 1ull);
                        v[6] += spc(z) - t * z;            // bce(sigm(z), t)
                    } else if (ch == 0) {
                        v[0] = spc(z) - r.tx * z;
                    } else if (ch == 1) {
                        v[1] = spc(z) - r.ty * z;
                    } else if (ch == 2) {
                        float d = z - r.tw; v[2] = d * d;
                    } else if (ch == 3) {
                        float d = z - r.th; v[3] = d * d;
                    } else {                               // ch == 4
                        v[4] = spc(-z);                    // bce(conf, 1)
                    }
                }
            }
            if (lane == 0) v[7] = 1.0f;                    // n_m count
        }
    }

    block_reduce9(v);
    __shared__ int s_amlast;
    if (tid == 0) {
#pragma unroll
        for (int k = 0; k < 9; k++) g_part[bid * 9 + k] = v[k];
        __threadfence();
        int t = atomicAdd(&g_count, 1);
        s_amlast = (t == GRID - 1);
    }
    __syncthreads();

    if (s_amlast) {
        float w[9];
#pragma unroll
        for (int k = 0; k < 9; k++) w[k] = 0.0f;
        for (int i = tid; i < GRID; i += 256) {
#pragma unroll
            for (int k = 0; k < 9; k++) w[k] += g_part[i * 9 + k];
        }
        block_reduce9(w);
        if (tid == 0) {
            float n_m  = w[7];
            float n_nm = (float)NCELL - w[8];
            float invN = 1.0f / (float)NCELL;
            float lx = w[0] * invN / n_m;
            float ly = w[1] * invN / n_m;
            float lw = w[2] * invN / n_m;
            float lh = w[3] * invN / n_m;
            float lconf = w[4] * invN / n_m + 0.5f * w[5] * invN / n_nm;
            float lcls  = w[6] / (n_m * (float)CC) / n_m;
            float loss  = 2.5f * (lx + ly) + 2.5f * (lw + lh) + lconf + lcls;
            out[0] = loss;
            out[1] = lx;
            out[2] = ly;
            out[3] = lw;
            out[4] = lh;
            out[5] = lconf;
            out[6] = lcls;
            g_count = 0;          // reset for next graph replay
            g_ready = 0;
        }
    }
}

// ---------------- launch ----------------
extern "C" void kernel_launch(void* const* d_in, const int* in_sizes, int n_in,
                              void* d_out, int out_size) {
    const float* inp = (const float*)d_in[0];   // (B, A*(5+C), H, W) fp32
    const float* tgt = (const float*)d_in[1];   // (B, T, 5) fp32
    float* out = (float*)d_out;                 // 7 fp32 scalars
    (void)in_sizes; (void)n_in; (void)out_size;

    k_all<<<GRID, 256>>>(inp, tgt, out);
}

// round 8
// speedup vs baseline: 5.3328x; 1.3161x over previous
#include <cuda_runtime.h>
#include <math.h>

// ---------------- problem constants ----------------
#define BB 16
#define AA 3
#define CC 80
#define HH 76
#define WW 76
#define TT 50
#define HWP (HH * WW)               // 5776
#define NCELL (BB * AA * HWP)       // 277248
#define NCH (5 + CC)                // 85
#define N4 (HWP / 4)                // 1444 float4 per plane
#define CONF_ITEMS (BB * AA * N4)   // 69312 float4 items

#define NB_CONF 136                 // 136*256 = 34816 threads, 2 float4 each
#define CONF_HALF (NB_CONF * 256)   // 34816
#define RECS_PER_SLICE 7            // 8 slices * 7 = 56 >= 50
#define NB_RECB (BB * 8)            // 128 record blocks
#define NB_FLAGB BB                 // 16 flag blocks
#define GRID (NB_CONF + NB_RECB + NB_FLAGB)   // 280

// anchors / stride = [[1.25,1.625],[2.0,3.75],[4.125,2.875]]
__constant__ float c_aw[3] = {1.25f, 2.0f, 4.125f};
__constant__ float c_ah[3] = {1.625f, 3.75f, 2.875f};

// ---------------- scratch ----------------
__device__ float g_part[GRID * 9];
__device__ int   g_count = 0;     // ticket; last block resets (graph-replay safe)

// ---------------- helpers ----------------
// softplus(z) = log(1+e^z); clamp mirrors max(log(.), -100) in reference
__device__ __forceinline__ float spc(float z) {
    return fminf(__logf(1.0f + __expf(z)), 100.0f);
}

// per-target geometry: cell/tx..th for best anchor, iou per anchor
__device__ __forceinline__ void target_info(
    float cls, float cx, float cy, float cw, float chv, int b,
    bool& valid, int& cell, float& tx, float& ty, float& tw, float& th,
    float iou[3], int& gi, int& gj)
{
    valid = (cls + cx + cy + cw + chv != 0.0f);
    cell = -1; tx = ty = tw = th = 0.0f;
    iou[0] = iou[1] = iou[2] = 0.0f; gi = 0; gj = 0;
    if (!valid) return;
    float gx = cx * WW, gy = cy * HH, gw = cw * WW, gh = chv * HH;
    gi = (int)gx; gj = (int)gy;
    float a1 = (gw + 1.0f) * (gh + 1.0f);
    int best = 0;
#pragma unroll
    for (int a = 0; a < 3; a++) {
        float iw = fmaxf(fminf(gw, c_aw[a]) + 1.0f, 0.0f);
        float ih = fmaxf(fminf(gh, c_ah[a]) + 1.0f, 0.0f);
        float inter = iw * ih;
        float a2 = (c_aw[a] + 1.0f) * (c_ah[a] + 1.0f);
        iou[a] = inter / (a1 + a2 - inter + 1e-16f);
        if (iou[a] > iou[best]) best = a;          // first-max tie-break
    }
    if (gj >= 0 && gj < HH && gi >= 0 && gi < WW) {
        cell = ((b * AA + best) * HH + gj) * WW + gi;
        tx = gx - (float)gi;
        ty = gy - (float)gj;
        tw = __logf(gw / c_aw[best] + 1e-16f);
        th = __logf(gh / c_ah[best] + 1e-16f);
    }
}

// Deterministic block reduction of 9 values. Thread 0 ends with totals in v[].
__device__ __forceinline__ void block_reduce9(float* v) {
    __shared__ float sh[8][9];
    int lane = threadIdx.x & 31;
    int wid  = threadIdx.x >> 5;
#pragma unroll
    for (int k = 0; k < 9; k++) {
        float x = v[k];
#pragma unroll
        for (int o = 16; o; o >>= 1) x += __shfl_down_sync(0xffffffffu, x, o);
        if (lane == 0) sh[wid][k] = x;
    }
    __syncthreads();
    if (wid == 0) {
#pragma unroll
        for (int k = 0; k < 9; k++) {
            float x = (lane < 8) ? sh[lane][k] : 0.0f;
#pragma unroll
            for (int o = 4; o; o >>= 1) x += __shfl_down_sync(0xffffffffu, x, o);
            if (lane == 0) v[k] = x;
        }
    }
}

// ---------------- fused kernel, all blocks independent ----------------
// v[0..3]=x/y/w/h sums, v[4]=bce(conf,1) masked, v[5]=Σ softplus(z4)
// (global, minus flagged), v[6]=cls sum, v[7]=n_m, v[8]=unique flagged count
__global__ void __launch_bounds__(256) k_all(const float* __restrict__ inp,
                                             const float* __restrict__ tgt,
                                             float* __restrict__ out) {
    __shared__ int   s_cell[TT];
    __shared__ int   s_cls[TT];
    __shared__ float s_tx[TT], s_ty[TT], s_tw[TT], s_th[TT];
    __shared__ int   s_flag[TT * 3];
    __shared__ int   s_wval[RECS_PER_SLICE];
    __shared__ int   s_woff[RECS_PER_SLICE];
    __shared__ float s_wtx[RECS_PER_SLICE], s_wty[RECS_PER_SLICE];
    __shared__ float s_wtw[RECS_PER_SLICE], s_wth[RECS_PER_SLICE];
    __shared__ unsigned long long s_wc0[RECS_PER_SLICE], s_wc1[RECS_PER_SLICE];

    int bid = blockIdx.x;
    int tid = threadIdx.x;
    float v[9];
#pragma unroll
    for (int k = 0; k < 9; k++) v[k] = 0.0f;

    if (bid < NB_CONF) {
        // ---------- conf planes: grouped softplus, 8 elems per log ----------
        float prod = 1.0f;
        int idx0 = bid * 256 + tid;                 // always < CONF_ITEMS
        {
            int plane = idx0 / N4;
            int off   = idx0 - plane * N4;
            const float4* p4 = (const float4*)(inp + ((size_t)plane * NCH + 4) * HWP);
            float4 z = __ldg(p4 + off);
            prod = (1.0f + __expf(z.x)) * (1.0f + __expf(z.y))
                 * (1.0f + __expf(z.z)) * (1.0f + __expf(z.w));
        }
        int idx1 = idx0 + CONF_HALF;
        if (idx1 < CONF_ITEMS) {
            int plane = idx1 / N4;
            int off   = idx1 - plane * N4;
            const float4* p4 = (const float4*)(inp + ((size_t)plane * NCH + 4) * HWP);
            float4 z = __ldg(p4 + off);
            prod *= (1.0f + __expf(z.x)) * (1.0f + __expf(z.y))
                  * (1.0f + __expf(z.z)) * (1.0f + __expf(z.w));
        }
        v[5] = __logf(prod);     // == Σ softplus over up to 8 elems
    } else if (bid < NB_CONF + NB_RECB) {
        // ---------- record blocks: 1 batch, <=7 records ----------
        int rb    = bid - NB_CONF;
        int b     = rb >> 3;
        int slice = rb & 7;

        // per-target compute (parallel, one thread per target)
        if (tid < TT) {
            const float* tp = tgt + (b * TT + tid) * 5;
            bool valid; int cell, gi, gj; float tx, ty, tw, th, iou[3];
            target_info(tp[0], tp[1], tp[2], tp[3], tp[4], b,
                        valid, cell, tx, ty, tw, th, iou, gi, gj);
            s_cell[tid] = cell;
            s_cls[tid]  = (int)tp[0];
            s_tx[tid] = tx; s_ty[tid] = ty; s_tw[tid] = tw; s_th[tid] = th;
        }
        __syncthreads();

        // winner resolution for my slice (last-update-wins, class union)
        if (tid < RECS_PER_SLICE) {
            int myrec = slice * RECS_PER_SLICE + tid;
            s_wval[tid] = 0;
            if (myrec < TT) {
                int cell = s_cell[myrec];
                if (cell >= 0) {
                    bool win = true;
                    unsigned long long c0 = 0ull, c1 = 0ull;
                    for (int j = 0; j < TT; j++) {
                        if (s_cell[j] == cell) {
                            if (j > myrec) win = false;
                            int ci = s_cls[j];
                            if (ci >= 0 && ci < 64)       c0 |= (1ull << ci);
                            else if (ci >= 64 && ci < CC) c1 |= (1ull << (ci - 64));
                        }
                    }
                    if (win) {
                        int gidx = cell / HWP;
                        int rr   = cell - gidx * HWP;
                        s_wval[tid] = 1;
                        s_woff[tid] = gidx * NCH * HWP + rr;
                        s_wtx[tid] = s_tx[myrec]; s_wty[tid] = s_ty[myrec];
                        s_wtw[tid] = s_tw[myrec]; s_wth[tid] = s_th[myrec];
                        s_wc0[tid] = c0; s_wc1[tid] = c1;
                        v[7] = 1.0f;                       // unique masked cell
                    }
                }
            }
        }
        __syncthreads();

        // heavy channel work: flattened item-parallel (good MLP)
        for (int it = tid; it < RECS_PER_SLICE * NCH; it += 256) {
            int r  = it / NCH;
            int ch = it - r * NCH;
            if (s_wval[r]) {
                float z = __ldg(inp + (size_t)s_woff[r] + (size_t)ch * HWP);
                if (ch >= 5) {
                    int c = ch - 5;
                    float t = (c < 64) ? (float)((s_wc0[r] >> c) & 1ull)
                                       : (float)((s_wc1[r] >> (c - 64)) & 1ull);
                    v[6] += spc(z) - t * z;                // bce(sigm(z), t)
                } else if (ch == 0) {
                    v[0] += spc(z) - s_wtx[r] * z;
                } else if (ch == 1) {
                    v[1] += spc(z) - s_wty[r] * z;
                } else if (ch == 2) {
                    float d = z - s_wtw[r]; v[2] += d * d;
                } else if (ch == 3) {
                    float d = z - s_wth[r]; v[3] += d * d;
                } else {                                   // ch == 4
                    v[4] += spc(-z);                       // bce(conf, 1)
                }
            }
        }
    } else {
        // ---------- flag blocks: noobj corrections, 1 batch ----------
        int b = bid - NB_CONF - NB_RECB;
        if (tid < TT * 3) {
            int q = tid / 3, a = tid - q * 3;
            const float* tp = tgt + (b * TT + q) * 5;
            bool valid; int cell, gi, gj; float tx, ty, tw, th, iou[3];
            target_info(tp[0], tp[1], tp[2], tp[3], tp[4], b,
                        valid, cell, tx, ty, tw, th, iou, gi, gj);
            int fl = -1;
            if (valid && iou[a] > 0.5f) {
                long nm = (((long)(b * AA + a) * HH + gj) * WW + gi);
                if (nm >= 0 && nm < NCELL) fl = (int)nm;
            }
            s_flag[tid] = fl;
        }
        __syncthreads();
        if (tid < TT * 3) {
            int cell = s_flag[tid];
            if (cell >= 0) {
                bool own = true;
                for (int j = 0; j < tid; j++)
                    if (s_flag[j] == cell) { own = false; break; }
                if (own) {
                    int gidx = cell / HWP;
                    int rr   = cell - gidx * HWP;
                    float z = __ldg(inp + ((size_t)gidx * NCH + 4) * HWP + rr);
                    v[5] = -spc(z);        // remove from global noobj sum
                    v[8] = 1.0f;           // unique flagged count
                }
            }
        }
    }

    block_reduce9(v);
    __shared__ int s_amlast;
    if (tid == 0) {
#pragma unroll
        for (int k = 0; k < 9; k++) g_part[bid * 9 + k] = v[k];
        __threadfence();
        int t = atomicAdd(&g_count, 1);
        s_amlast = (t == GRID - 1);
    }
    __syncthreads();

    if (s_amlast) {
        float w[9];
#pragma unroll
        for (int k = 0; k < 9; k++) w[k] = 0.0f;
        for (int i = tid; i < GRID; i += 256) {
#pragma unroll
            for (int k = 0; k < 9; k++) w[k] += g_part[i * 9 + k];
        }
        block_reduce9(w);
        if (tid == 0) {
            float n_m  = w[7];
            float n_nm = (float)NCELL - w[8];
            float invN = 1.0f / (float)NCELL;
            float lx = w[0] * invN / n_m;
            float ly = w[1] * invN / n_m;
            float lw = w[2] * invN / n_m;
            float lh = w[3] * invN / n_m;
            float lconf = w[4] * invN / n_m + 0.5f * w[5] * invN / n_nm;
            float lcls  = w[6] / (n_m * (float)CC) / n_m;
            float loss  = 2.5f * (lx + ly) + 2.5f * (lw + lh) + lconf + lcls;
            out[0] = loss;
            out[1] = lx;
            out[2] = ly;
            out[3] = lw;
            out[4] = lh;
            out[5] = lconf;
            out[6] = lcls;
            g_count = 0;          // reset for next graph replay
        }
    }
}

// ---------------- launch ----------------
extern "C" void kernel_launch(void* const* d_in, const int* in_sizes, int n_in,
                              void* d_out, int out_size) {
    const float* inp = (const float*)d_in[0];   // (B, A*(5+C), H, W) fp32
    const float* tgt = (const float*)d_in[1];   // (B, T, 5) fp32
    float* out = (float*)d_out;                 // 7 fp32 scalars
    (void)in_sizes; (void)n_in; (void)out_size;

    k_all<<<GRID, 256>>>(inp, tgt, out);
}

// round 11
// speedup vs baseline: 6.8047x; 1.2760x over previous
#include <cuda_runtime.h>
#include <math.h>

// ---------------- problem constants ----------------
#define BB 16
#define AA 3
#define CC 80
#define HH 76
#define WW 76
#define TT 50
#define HWP (HH * WW)               // 5776
#define NCELL (BB * AA * HWP)       // 277248
#define NCH (5 + CC)                // 85
#define N4 (HWP / 4)                // 1444 float4 per plane
#define CONF_ITEMS (BB * AA * N4)   // 69312 float4 items

#define NB_CONF 136                 // 136*256 threads, 2 float4 each
#define CONF_HALF (NB_CONF * 256)   // 34816
#define RPS 13                      // records per slice
#define NSLICE 4                    // 4*13 = 52 >= 50
#define NB_RECB (BB * NSLICE)       // 64 record blocks
#define NB_FLAGB BB                 // 16 flag blocks
#define GRID (NB_CONF + NB_RECB + NB_FLAGB)   // 216

#define FIXSCALE 268435456.0f       // 2^28
#define INVSCALE (1.0 / 268435456.0)

// anchors / stride = [[1.25,1.625],[2.0,3.75],[4.125,2.875]]
__constant__ float c_aw[3] = {1.25f, 2.0f, 4.125f};
__constant__ float c_ah[3] = {1.625f, 3.75f, 2.875f};

// ---------------- scratch ----------------
__device__ unsigned long long g_acc[9];   // fixed-point accumulators (zero-init)
__device__ int g_count = 0;               // ticket; last block resets

// ---------------- helpers ----------------
// softplus(z) = log(1+e^z); clamp mirrors max(log(.), -100) in reference
__device__ __forceinline__ float spc(float z) {
    return fminf(__logf(1.0f + __expf(z)), 100.0f);
}

// per-target geometry
__device__ __forceinline__ void target_info(
    float cls, float cx, float cy, float cw, float chv, int b,
    bool& valid, int& cell, float& tx, float& ty, float& tw, float& th,
    float iou[3], int& gi, int& gj)
{
    valid = (cls + cx + cy + cw + chv != 0.0f);
    cell = -1; tx = ty = tw = th = 0.0f;
    iou[0] = iou[1] = iou[2] = 0.0f; gi = 0; gj = 0;
    if (!valid) return;
    float gx = cx * WW, gy = cy * HH, gw = cw * WW, gh = chv * HH;
    gi = (int)gx; gj = (int)gy;
    float a1 = (gw + 1.0f) * (gh + 1.0f);
    int best = 0;
#pragma unroll
    for (int a = 0; a < 3; a++) {
        float iw = fmaxf(fminf(gw, c_aw[a]) + 1.0f, 0.0f);
        float ih = fmaxf(fminf(gh, c_ah[a]) + 1.0f, 0.0f);
        float inter = iw * ih;
        float a2 = (c_aw[a] + 1.0f) * (c_ah[a] + 1.0f);
        iou[a] = inter / (a1 + a2 - inter + 1e-16f);
        if (iou[a] > iou[best]) best = a;          // first-max tie-break
    }
    if (gj >= 0 && gj < HH && gi >= 0 && gi < WW) {
        cell = ((b * AA + best) * HH + gj) * WW + gi;
        tx = gx - (float)gi;
        ty = gy - (float)gj;
        tw = __logf(gw / c_aw[best] + 1e-16f);
        th = __logf(gh / c_ah[best] + 1e-16f);
    }
}

// Deterministic block reduction of 9 values. Thread 0 ends with totals in v[].
__device__ __forceinline__ void block_reduce9(float* v) {
    __shared__ float sh[8][9];
    int lane = threadIdx.x & 31;
    int wid  = threadIdx.x >> 5;
#pragma unroll
    for (int k = 0; k < 9; k++) {
        float x = v[k];
#pragma unroll
        for (int o = 16; o; o >>= 1) x += __shfl_down_sync(0xffffffffu, x, o);
        if (lane == 0) sh[wid][k] = x;
    }
    __syncthreads();
    if (wid == 0) {
#pragma unroll
        for (int k = 0; k < 9; k++) {
            float x = (lane < 8) ? sh[lane][k] : 0.0f;
#pragma unroll
            for (int o = 4; o; o >>= 1) x += __shfl_down_sync(0xffffffffu, x, o);
            if (lane == 0) v[k] = x;
        }
    }
}

// ---------------- fused kernel, all blocks independent ----------------
// v[0..3]=x/y/w/h sums, v[4]=bce(conf,1) masked, v[5]=Σ softplus(z4)
// (global, minus flagged), v[6]=cls sum, v[7]=n_m, v[8]=unique flagged count
__global__ void __launch_bounds__(256) k_all(const float* __restrict__ inp,
                                             const float* __restrict__ tgt,
                                             float* __restrict__ out) {
    __shared__ int   s_cell[TT];
    __shared__ int   s_cls[TT];
    __shared__ float s_tx[TT], s_ty[TT], s_tw[TT], s_th[TT];
    __shared__ int   s_flag[TT * 3];
    __shared__ int   s_n;
    __shared__ int   s_woff[RPS];
    __shared__ float s_wtx[RPS], s_wty[RPS], s_wtw[RPS], s_wth[RPS];
    __shared__ unsigned long long s_wc0[RPS], s_wc1[RPS];

    int bid = blockIdx.x;
    int tid = threadIdx.x;
    float v[9];
#pragma unroll
    for (int k = 0; k < 9; k++) v[k] = 0.0f;

    if (bid < NB_CONF) {
        // ---------- conf planes: grouped softplus, 8 elems per log ----------
        float prod = 1.0f;
        int idx0 = bid * 256 + tid;                 // always < CONF_ITEMS
        {
            int plane = idx0 / N4;
            int off   = idx0 - plane * N4;
            const float4* p4 = (const float4*)(inp + ((size_t)plane * NCH + 4) * HWP);
            float4 z = __ldg(p4 + off);
            prod = (1.0f + __expf(z.x)) * (1.0f + __expf(z.y))
                 * (1.0f + __expf(z.z)) * (1.0f + __expf(z.w));
        }
        int idx1 = idx0 + CONF_HALF;
        if (idx1 < CONF_ITEMS) {
            int plane = idx1 / N4;
            int off   = idx1 - plane * N4;
            const float4* p4 = (const float4*)(inp + ((size_t)plane * NCH + 4) * HWP);
            float4 z = __ldg(p4 + off);
            prod *= (1.0f + __expf(z.x)) * (1.0f + __expf(z.y))
                  * (1.0f + __expf(z.z)) * (1.0f + __expf(z.w));
        }
        v[5] = __logf(prod);     // == Σ softplus over up to 8 elems
    } else if (bid < NB_CONF + NB_RECB) {
        // ---------- record blocks: 1 batch, <=13 records ----------
        int rb    = bid - NB_CONF;
        int b     = rb >> 2;           // /NSLICE
        int slice = rb & 3;

        // phase 1: per-target compute (one thread per target)
        if (tid < TT) {
            const float* tp = tgt + (b * TT + tid) * 5;
            bool valid; int cell, gi, gj; float tx, ty, tw, th, iou[3];
            target_info(tp[0], tp[1], tp[2], tp[3], tp[4], b,
                        valid, cell, tx, ty, tw, th, iou, gi, gj);
            s_cell[tid] = cell;
            s_cls[tid]  = (int)tp[0];
            s_tx[tid] = tx; s_ty[tid] = ty; s_tw[tid] = tw; s_th[tid] = th;
        }
        __syncthreads();

        // phase 2: winner resolution + deterministic warp-ballot compaction
        if (tid < 32) {
            int myrec = slice * RPS + tid;
            bool win = false;
            unsigned long long c0 = 0ull, c1 = 0ull;
            if (tid < RPS && myrec < TT) {
                int cell = s_cell[myrec];
                if (cell >= 0) {
                    win = true;
                    for (int j = 0; j < TT; j++) {
                        if (s_cell[j] == cell) {
                            if (j > myrec) win = false;   // last-update wins box
                            int ci = s_cls[j];            // union ALL class bits
                            if (ci >= 0 && ci < 64)       c0 |= (1ull << ci);
                            else if (ci >= 64 && ci < CC) c1 |= (1ull << (ci - 64));
                        }
                    }
                }
            }
            unsigned m = __ballot_sync(0xffffffffu, win);
            if (win) {
                int slot = __popc(m & ((1u << tid) - 1u));
                int cell = s_cell[myrec];
                int gidx = cell / HWP;
                int rr   = cell - gidx * HWP;
                s_woff[slot] = gidx * NCH * HWP + rr;
                s_wtx[slot] = s_tx[myrec]; s_wty[slot] = s_ty[myrec];
                s_wtw[slot] = s_tw[myrec]; s_wth[slot] = s_th[myrec];
                s_wc0[slot] = c0; s_wc1[slot] = c1;
                v[7] = 1.0f;                               // unique masked cell
            }
            if (tid == 0) s_n = __popc(m);
        }
        __syncthreads();

        // phase 3: dense channel work with explicit MLP=5 prefetch
        int nit = s_n * NCH;                               // <= 1105
        float zz[5]; int rr_[5], cc_[5]; bool pp[5];
#pragma unroll
        for (int k = 0; k < 5; k++) {
            int idx = tid + k * 256;
            pp[k] = (idx < nit);
            if (pp[k]) {
                int r  = idx / NCH;
                int ch = idx - r * NCH;
                rr_[k] = r; cc_[k] = ch;
                zz[k] = __ldg(inp + (size_t)s_woff[r] + (size_t)ch * HWP);
            }
        }
#pragma unroll
        for (int k = 0; k < 5; k++) {
            if (pp[k]) {
                int r = rr_[k], ch = cc_[k];
                float z = zz[k];
                if (ch >= 5) {
                    int c = ch - 5;
                    float t = (c < 64) ? (float)((s_wc0[r] >> c) & 1ull)
                                       : (float)((s_wc1[r] >> (c - 64)) & 1ull);
                    v[6] += spc(z) - t * z;                // bce(sigm(z), t)
                } else if (ch == 0) {
                    v[0] += spc(z) - s_wtx[r] * z;
                } else if (ch == 1) {
                    v[1] += spc(z) - s_wty[r] * z;
                } else if (ch == 2) {
                    float d = z - s_wtw[r]; v[2] += d * d;
                } else if (ch == 3) {
                    float d = z - s_wth[r]; v[3] += d * d;
                } else {                                   // ch == 4
                    v[4] += spc(-z);                       // bce(conf, 1)
                }
            }
        }
    } else {
        // ---------- flag blocks: noobj corrections, 1 batch ----------
        int b = bid - NB_CONF - NB_RECB;
        if (tid < TT * 3) {
            int q = tid / 3, a = tid - q * 3;
            const float* tp = tgt + (b * TT + q) * 5;
            bool valid; int cell, gi, gj; float tx, ty, tw, th, iou[3];
            target_info(tp[0], tp[1], tp[2], tp[3], tp[4], b,
                        valid, cell, tx, ty, tw, th, iou, gi, gj);
            int fl = -1;
            if (valid && iou[a] > 0.5f) {
                long nm = (((long)(b * AA + a) * HH + gj) * WW + gi);
                if (nm >= 0 && nm < NCELL) fl = (int)nm;
            }
            s_flag[tid] = fl;
        }
        __syncthreads();
        if (tid < TT * 3) {
            int cell = s_flag[tid];
            if (cell >= 0) {
                bool own = true;
                for (int j = 0; j < tid; j++)
                    if (s_flag[j] == cell) { own = false; break; }
                if (own) {
                    int gidx = cell / HWP;
                    int rr   = cell - gidx * HWP;
                    float z = __ldg(inp + ((size_t)gidx * NCH + 4) * HWP + rr);
                    v[5] = -spc(z);        // remove from global noobj sum
                    v[8] = 1.0f;           // unique flagged count
                }
            }
        }
    }

    // ---------- deterministic fixed-point global accumulation ----------
    block_reduce9(v);
    __shared__ int s_amlast;
    if (tid == 0) {
#pragma unroll
        for (int k = 0; k < 9; k++) {
            long long q = __float2ll_rn(v[k] * FIXSCALE);
            atomicAdd(&g_acc[k], (unsigned long long)q);
        }
        __threadfence();
        int t = atomicAdd(&g_count, 1);
        s_amlast = (t == GRID - 1);
    }
    __syncthreads();

    if (s_amlast && tid == 0) {
        __threadfence();
        double w[9];
#pragma unroll
        for (int k = 0; k < 9; k++)
            w[k] = (double)(long long)g_acc[k] * INVSCALE;
        float n_m  = (float)w[7];
        float n_nm = (float)NCELL - (float)w[8];
        float invN = 1.0f / (float)NCELL;
        float lx = (float)w[0] * invN / n_m;
        float ly = (float)w[1] * invN / n_m;
        float lw = (float)w[2] * invN / n_m;
        float lh = (float)w[3] * invN / n_m;
        float lconf = (float)w[4] * invN / n_m + 0.5f * (float)w[5] * invN / n_nm;
        float lcls  = (float)w[6] / (n_m * (float)CC) / n_m;
        float loss  = 2.5f * (lx + ly) + 2.5f * (lw + lh) + lconf + lcls;
        out[0] = loss;
        out[1] = lx;
        out[2] = ly;
        out[3] = lw;
        out[4] = lh;
        out[5] = lconf;
        out[6] = lcls;
#pragma unroll
        for (int k = 0; k < 9; k++) g_acc[k] = 0ull;   // reset for next replay
        g_count = 0;
    }
}

// ---------------- launch ----------------
extern "C" void kernel_launch(void* const* d_in, const int* in_sizes, int n_in,
                              void* d_out, int out_size) {
    const float* inp = (const float*)d_in[0];   // (B, A*(5+C), H, W) fp32
    const float* tgt = (const float*)d_in[1];   // (B, T, 5) fp32
    float* out = (float*)d_out;                 // 7 fp32 scalars
    (void)in_sizes; (void)n_in; (void)out_size;

    k_all<<<GRID, 256>>>(inp, tgt, out);
}